// round 14
// baseline (speedup 1.0000x reference)
#include <cuda_runtime.h>
#include <cuda_fp16.h>
#include <math.h>
#include <stdint.h>

#define B_ 4
#define S_ 2048
#define D_ 768
#define H_ 12
#define DH_ 64
#define M_TOT (B_ * S_)          // 8192
#define NELEM (M_TOT * D_)       // 6291456
#define DD (D_ * D_)             // 589824

typedef unsigned short u16;
typedef unsigned int u32;

__device__ u16 g_Q[NELEM];
__device__ u16 g_K[NELEM];
__device__ u16 g_V[NELEM];
__device__ u16 g_C[NELEM];
__device__ u16 g_X[NELEM];
__device__ u16 g_W[4 * DD];

// Q prescale: 1/8 (score scale) * log2(e) (exp -> ex2 domain)
#define QSCALE 0.18033688011112042f
// ln2^2: converts (s*log2e)^2 back to s^2 in the relu^2 branch
#define LN2SQ 0.4804530139182014f

// ---------------------------------------------------------------------------
__device__ __forceinline__ u32 h2pack(float lo, float hi) {
    u32 r;
    asm("cvt.rn.f16x2.f32 %0, %1, %2;" : "=r"(r) : "f"(hi), "f"(lo));
    return r;
}

__device__ __forceinline__ u32 ex2h2(u32 x) {
    u32 r;
    asm("ex2.approx.f16x2 %0, %1;" : "=r"(r) : "r"(x));
    return r;
}

__device__ __forceinline__ u32 relusq_h2(u32 x) {
    u32 m, r;
    asm("max.f16x2 %0, %1, %2;" : "=r"(m) : "r"(x), "r"(0u));
    asm("mul.f16x2 %0, %1, %1;" : "=r"(r) : "r"(m));
    return r;
}

// NOTE: non-volatile on purpose — pure register op, deps via constraints.
// Lets the compiler interleave HMMAs with LDSM/ALU freely.
__device__ __forceinline__ void mma16(float* c, u32 a0, u32 a1, u32 a2, u32 a3,
                                      u32 b0, u32 b1) {
    asm("mma.sync.aligned.m16n8k16.row.col.f32.f16.f16.f32 "
        "{%0,%1,%2,%3},{%4,%5,%6,%7},{%8,%9},{%0,%1,%2,%3};\n"
        : "+f"(c[0]), "+f"(c[1]), "+f"(c[2]), "+f"(c[3])
        : "r"(a0), "r"(a1), "r"(a2), "r"(a3), "r"(b0), "r"(b1));
}

__device__ __forceinline__ void ldsm4(u32& r0, u32& r1, u32& r2, u32& r3, u32 addr) {
    asm volatile("ldmatrix.sync.aligned.m8n8.x4.shared.b16 {%0,%1,%2,%3}, [%4];"
                 : "=r"(r0), "=r"(r1), "=r"(r2), "=r"(r3) : "r"(addr));
}

__device__ __forceinline__ void ldsm4t(u32& r0, u32& r1, u32& r2, u32& r3, u32 addr) {
    asm volatile("ldmatrix.sync.aligned.m8n8.x4.trans.shared.b16 {%0,%1,%2,%3}, [%4];"
                 : "=r"(r0), "=r"(r1), "=r"(r2), "=r"(r3) : "r"(addr));
}

__device__ __forceinline__ void cp16(unsigned dst, const void* src) {
    asm volatile("cp.async.cg.shared.global [%0], [%1], 16;" :: "r"(dst), "l"(src));
}
#define CP_COMMIT() asm volatile("cp.async.commit_group;")
#define CP_WAIT(N) asm volatile("cp.async.wait_group %0;" :: "n"(N))

__device__ __forceinline__ unsigned smem_u32(const void* p) {
    unsigned a;
    asm("{ .reg .u64 t; cvta.to.shared.u64 t, %1; cvt.u32.u64 %0, t; }" : "=r"(a) : "l"(p));
    return a;
}

// ---------------------------------------------------------------------------
// Prepass: RN-round hidden_states and 4 weights to fp16.
// ---------------------------------------------------------------------------
__global__ void to_half_pre(const float* __restrict__ hs,
                            const float* __restrict__ Wq, const float* __restrict__ Wk,
                            const float* __restrict__ Wv, const float* __restrict__ Wo,
                            u16* __restrict__ X, u16* __restrict__ W)
{
    const int i = blockIdx.x * blockDim.x + threadIdx.x;
    const int stride = gridDim.x * blockDim.x;
    for (int j = i; j < NELEM / 4; j += stride) {
        float4 v = ((const float4*)hs)[j];
        uint2 o = {h2pack(v.x, v.y), h2pack(v.z, v.w)};
        ((uint2*)X)[j] = o;
    }
    const float* src[4] = {Wq, Wk, Wv, Wo};
#pragma unroll
    for (int w = 0; w < 4; w++) {
        const float4* s = (const float4*)src[w];
        uint2* d = (uint2*)(W + (size_t)w * DD);
        for (int j = i; j < DD / 4; j += stride) {
            float4 v = s[j];
            uint2 o = {h2pack(v.x, v.y), h2pack(v.z, v.w)};
            d[j] = o;
        }
    }
}

// ---------------------------------------------------------------------------
// fp16 GEMM: 128x128 tiles, BK=64, 256 threads, 2x4 warp grid (64x32 warp
// tiles), 3-stage cp.async ring; loads issued BEFORE the wait each slab.
// ---------------------------------------------------------------------------
#define GPH 72
#define GSTGH (128 * GPH)
#define GSTGB (GSTGH * 2 * 2)        // bytes per stage (A+B) = 36864
#define GEMM_SM (3 * GSTGB)          // 110592 bytes

__device__ __forceinline__ void gemm_h_body(
    const u16* __restrict__ X, const u16* __restrict__ W,
    const float* __restrict__ bi, void* __restrict__ Yp,
    int half_out, float oscale, u16* gsm)
{
    const unsigned sb = smem_u32(gsm);
    const int tid = threadIdx.x;
    const int lane = tid & 31, wid = tid >> 5;
    const int g = lane >> 2, tig = lane & 3;
    const int wy = wid >> 2, wx = wid & 3;
    const int m0 = blockIdx.y * 128, n0 = blockIdx.x * 128;

#define GH_LOAD(s_) do {                                                        \
        int st_ = (s_) % 3;                                                     \
        unsigned ab_ = sb + st_ * GSTGB;                                        \
        unsigned bb_ = ab_ + GSTGH * 2;                                         \
        _Pragma("unroll")                                                       \
        for (int u_ = 0; u_ < 4; u_++) {                                        \
            int ch_ = tid + u_ * 256;                                           \
            int r_ = ch_ >> 3, c_ = ch_ & 7;                                    \
            cp16(ab_ + r_ * 144 + c_ * 16,                                      \
                 X + (size_t)(m0 + r_) * D_ + (s_) * 64 + c_ * 8);              \
            cp16(bb_ + r_ * 144 + c_ * 16,                                      \
                 W + (size_t)(n0 + r_) * D_ + (s_) * 64 + c_ * 8);              \
        }                                                                       \
        CP_COMMIT();                                                            \
    } while (0)

    GH_LOAD(0);
    GH_LOAD(1);

    float acc[4][4][4] = {};
    const int NSLAB = D_ / 64;   // 12

    const unsigned a_lrow = (lane & 15) * 144 + (lane >> 4) * 16;
    const unsigned b_lrow = (lane & 7) * 144 + (lane >> 3) * 16;

    for (int s = 0; s < NSLAB; s++) {
        __syncthreads();
        if (s + 2 < NSLAB) {
            GH_LOAD(s + 2);       // issue before waiting: 3 groups in flight
            CP_WAIT(2);
        } else if (s + 1 < NSLAB) {
            CP_WAIT(1);
        } else {
            CP_WAIT(0);
        }
        __syncthreads();

        const unsigned ab = sb + (s % 3) * GSTGB;
        const unsigned bb = ab + GSTGH * 2;
        const unsigned abase = ab + (wy * 64) * 144 + a_lrow;
        const unsigned bbase = bb + (wx * 32) * 144 + b_lrow;

#pragma unroll
        for (int ksp = 0; ksp < 2; ksp++) {
            u32 b[4][4];
#pragma unroll
            for (int nt = 0; nt < 4; nt++)
                ldsm4(b[nt][0], b[nt][1], b[nt][2], b[nt][3],
                      bbase + nt * 8 * 144 + ksp * 64);
#pragma unroll
            for (int kh = 0; kh < 2; kh++) {
                const int ks = 2 * ksp + kh;
                u32 a[4][4];
#pragma unroll
                for (int mt = 0; mt < 4; mt++)
                    ldsm4(a[mt][0], a[mt][1], a[mt][2], a[mt][3],
                          abase + mt * 16 * 144 + ks * 32);
#pragma unroll
                for (int mt = 0; mt < 4; mt++)
#pragma unroll
                    for (int nt = 0; nt < 4; nt++)
                        mma16(acc[mt][nt], a[mt][0], a[mt][1], a[mt][2], a[mt][3],
                              b[nt][2 * kh], b[nt][2 * kh + 1]);
            }
        }
    }

#pragma unroll
    for (int nt = 0; nt < 4; nt++) {
        int c = n0 + wx * 32 + nt * 8 + 2 * tig;
        float b0v = bi[c], b1v = bi[c + 1];
#pragma unroll
        for (int mt = 0; mt < 4; mt++) {
            int r = m0 + wy * 64 + mt * 16 + g;
            float o0 = acc[mt][nt][0] + b0v;
            float o1 = acc[mt][nt][1] + b1v;
            float o2 = acc[mt][nt][2] + b0v;
            float o3 = acc[mt][nt][3] + b1v;
            if (half_out) {
                u16* Yh = (u16*)Yp;
                *(u32*)&Yh[(size_t)r * D_ + c] = h2pack(o0 * oscale, o1 * oscale);
                *(u32*)&Yh[(size_t)(r + 8) * D_ + c] = h2pack(o2 * oscale, o3 * oscale);
            } else {
                float* Yf = (float*)Yp;
                float2 q0 = {o0, o1}, q1 = {o2, o3};
                *(float2*)&Yf[(size_t)r * D_ + c] = q0;
                *(float2*)&Yf[(size_t)(r + 8) * D_ + c] = q1;
            }
        }
    }
#undef GH_LOAD
}

__global__ __launch_bounds__(256, 2) void gemm_qkv_h(
    const u16* __restrict__ X,
    const u16* __restrict__ Wh, const float* __restrict__ bq,
    const float* __restrict__ bk, const float* __restrict__ bv,
    u16* __restrict__ Yq, u16* __restrict__ Yk, u16* __restrict__ Yv)
{
    extern __shared__ u16 gsm[];
    const u16* W; const float* bi; u16* Y; float sc;
    if (blockIdx.z == 0)      { W = Wh;          bi = bq; Y = Yq; sc = QSCALE; }
    else if (blockIdx.z == 1) { W = Wh + DD;     bi = bk; Y = Yk; sc = 1.0f; }
    else                      { W = Wh + 2 * DD; bi = bv; Y = Yv; sc = 1.0f; }
    gemm_h_body(X, W, bi, Y, 1, sc, gsm);
}

__global__ __launch_bounds__(256, 2) void gemm_out_h(
    const u16* __restrict__ X, const u16* __restrict__ Wh,
    const float* __restrict__ bo, float* __restrict__ Y)
{
    extern __shared__ u16 gsm[];
    gemm_h_body(X, Wh, bo, Y, 0, 1.0f, gsm);
}

// ---------------------------------------------------------------------------
// Attention fp16 v7: as v6 + load-before-wait + non-volatile MMA scheduling.
// ---------------------------------------------------------------------------
#define KPH 72
#define KTILE 128
#define KBUFB (KTILE * 144)          // 18432 B per operand stage
#define OFF_VB (3 * KBUFB)
#define ATT_SM (6 * KBUFB)           // 110592 B
#define NKT (S_ / KTILE)             // 16

__global__ __launch_bounds__(256, 2) void attn_h(
    const u16* __restrict__ Q, const u16* __restrict__ K,
    const u16* __restrict__ V, const float* __restrict__ wmix,
    u16* __restrict__ C)
{
    extern __shared__ u16 sm[];
    const unsigned sbase = smem_u32(sm);

    const int tid = threadIdx.x;
    const int lane = tid & 31, w = tid >> 5;
    const int g = lane >> 2, tig = lane & 3;
    const int s0 = blockIdx.x * 128;
    const int h = blockIdx.y;
    const int b = blockIdx.z;
    const size_t base = (size_t)b * S_ * D_ + (size_t)h * DH_;

    const u16* kgb = K + base;
    const u16* vgb = V + base;

    const int lrow = tid >> 3;
    const int lseg = tid & 7;

#define ATT_LOAD(kt_) do {                                                      \
        int st_ = (kt_) % 3;                                                    \
        unsigned sk_ = sbase + st_ * KBUFB;                                     \
        unsigned sv_ = sbase + OFF_VB + st_ * KBUFB;                            \
        const u16* kg_ = kgb + (size_t)(kt_) * KTILE * D_;                      \
        const u16* vg_ = vgb + (size_t)(kt_) * KTILE * D_;                      \
        _Pragma("unroll")                                                       \
        for (int u_ = 0; u_ < 4; u_++) {                                        \
            int row_ = lrow + u_ * 32;                                          \
            cp16(sk_ + row_ * 144 + lseg * 16, kg_ + (size_t)row_ * D_ + lseg * 8); \
            cp16(sv_ + row_ * 144 + lseg * 16, vg_ + (size_t)row_ * D_ + lseg * 8); \
        }                                                                       \
        CP_COMMIT();                                                            \
    } while (0)

    ATT_LOAD(0);
    ATT_LOAD(1);

    // Persistent Q fragments (Q pre-scaled by 0.125*log2e)
    u32 qA[4][4];
    {
        const u16* qp = Q + base + (size_t)(s0 + w * 16 + g) * D_;
        const u16* qp8 = qp + 8 * D_;
#pragma unroll
        for (int ks = 0; ks < 4; ks++) {
            qA[ks][0] = *(const u32*)(qp + ks * 16 + 2 * tig);
            qA[ks][1] = *(const u32*)(qp8 + ks * 16 + 2 * tig);
            qA[ks][2] = *(const u32*)(qp + ks * 16 + 8 + 2 * tig);
            qA[ks][3] = *(const u32*)(qp8 + ks * 16 + 8 + 2 * tig);
        }
    }

    float e0 = __expf(wmix[0]), e1 = __expf(wmix[1]);
    float inv = 1.0f / (e0 + e1);
    const float mix0 = e0 * inv;
    const float mix1l = e1 * inv * LN2SQ;

    float os[8][4] = {};
    float orl[8][4] = {};
    float ls[4] = {};
    const u32 oneb = (g == 0) ? 0x3C003C00u : 0u;

    const unsigned k_lrow = (lane & 7) * 144 + (lane >> 3) * 16;
    const unsigned v_lrow = (lane & 15) * 144 + (lane >> 4) * 16;

    for (int kt = 0; kt < NKT; kt++) {
        __syncthreads();
        if (kt + 2 < NKT) {
            ATT_LOAD(kt + 2);     // issue before waiting
            CP_WAIT(2);
        } else if (kt + 1 < NKT) {
            CP_WAIT(1);
        } else {
            CP_WAIT(0);
        }
        __syncthreads();

        const unsigned skb = sbase + (kt % 3) * KBUFB;
        const unsigned svb = sbase + OFF_VB + (kt % 3) * KBUFB;

#pragma unroll
        for (int kvg = 0; kvg < 8; kvg++) {
            float sce[4] = {0.f, 0.f, 0.f, 0.f};
            float sco[4] = {0.f, 0.f, 0.f, 0.f};
            const unsigned kbb = skb + (kvg * 16) * 144 + k_lrow;
#pragma unroll
            for (int ksp = 0; ksp < 2; ksp++) {
                u32 be0, be1, be2, be3, bo0, bo1, bo2, bo3;
                ldsm4(be0, be1, be2, be3, kbb + ksp * 64);
                ldsm4(bo0, bo1, bo2, bo3, kbb + 8 * 144 + ksp * 64);
                const int ks = 2 * ksp;
                mma16(sce, qA[ks][0], qA[ks][1], qA[ks][2], qA[ks][3], be0, be1);
                mma16(sce, qA[ks + 1][0], qA[ks + 1][1], qA[ks + 1][2], qA[ks + 1][3], be2, be3);
                mma16(sco, qA[ks][0], qA[ks][1], qA[ks][2], qA[ks][3], bo0, bo1);
                mma16(sco, qA[ks + 1][0], qA[ks + 1][1], qA[ks + 1][2], qA[ks + 1][3], bo2, bo3);
            }

            const unsigned vbb = svb + (kvg * 16) * 144 + v_lrow;
            u32 va0, va1, va2, va3;
            ldsm4t(va0, va1, va2, va3, vbb);

            u32 spe0 = h2pack(sce[0], sce[1]);
            u32 spe1 = h2pack(sce[2], sce[3]);
            u32 spo0 = h2pack(sco[0], sco[1]);
            u32 spo1 = h2pack(sco[2], sco[3]);

            u32 ape0 = ex2h2(spe0);
            u32 ape1 = ex2h2(spe1);
            u32 ape2 = ex2h2(spo0);
            u32 ape3 = ex2h2(spo1);

            u32 apq0 = relusq_h2(spe0);
            u32 apq1 = relusq_h2(spe1);
            u32 apq2 = relusq_h2(spo0);
            u32 apq3 = relusq_h2(spo1);

            mma16(ls, ape0, ape1, ape2, ape3, oneb, oneb);

            u32 vb0, vb1, vb2, vb3;
            ldsm4t(vb0, vb1, vb2, vb3, vbb + 32);

            mma16(os[0], ape0, ape1, ape2, ape3, va0, va1);
            mma16(orl[0], apq0, apq1, apq2, apq3, va0, va1);
            mma16(os[1], ape0, ape1, ape2, ape3, va2, va3);
            mma16(orl[1], apq0, apq1, apq2, apq3, va2, va3);

            ldsm4t(va0, va1, va2, va3, vbb + 64);

            mma16(os[2], ape0, ape1, ape2, ape3, vb0, vb1);
            mma16(orl[2], apq0, apq1, apq2, apq3, vb0, vb1);
            mma16(os[3], ape0, ape1, ape2, ape3, vb2, vb3);
            mma16(orl[3], apq0, apq1, apq2, apq3, vb2, vb3);

            ldsm4t(vb0, vb1, vb2, vb3, vbb + 96);

            mma16(os[4], ape0, ape1, ape2, ape3, va0, va1);
            mma16(orl[4], apq0, apq1, apq2, apq3, va0, va1);
            mma16(os[5], ape0, ape1, ape2, ape3, va2, va3);
            mma16(orl[5], apq0, apq1, apq2, apq3, va2, va3);

            mma16(os[6], ape0, ape1, ape2, ape3, vb0, vb1);
            mma16(orl[6], apq0, apq1, apq2, apq3, vb0, vb1);
            mma16(os[7], ape0, ape1, ape2, ape3, vb2, vb3);
            mma16(orl[7], apq0, apq1, apq2, apq3, vb2, vb3);
        }
    }

    float l0 = __shfl_sync(0xffffffffu, ls[0], lane & 28);
    float l1 = __shfl_sync(0xffffffffu, ls[2], lane & 28);
    float f0 = mix0 / l0;
    float f1 = mix0 / l1;

    u16* crow = C + base + (size_t)(s0 + w * 16 + g) * D_;
    u16* crow8 = crow + 8 * D_;
#pragma unroll
    for (int dt = 0; dt < 8; dt++) {
        *(u32*)&crow[dt * 8 + 2 * tig] =
            h2pack(os[dt][0] * f0 + orl[dt][0] * mix1l,
                   os[dt][1] * f0 + orl[dt][1] * mix1l);
        *(u32*)&crow8[dt * 8 + 2 * tig] =
            h2pack(os[dt][2] * f1 + orl[dt][2] * mix1l,
                   os[dt][3] * f1 + orl[dt][3] * mix1l);
    }
#undef ATT_LOAD
}

// ---------------------------------------------------------------------------
extern "C" void kernel_launch(void* const* d_in, const int* in_sizes, int n_in,
                              void* d_out, int out_size)
{
    const float* hs   = (const float*)d_in[0];
    const float* Wq   = (const float*)d_in[1];
    const float* bq   = (const float*)d_in[2];
    const float* Wk   = (const float*)d_in[3];
    const float* bk   = (const float*)d_in[4];
    const float* Wv   = (const float*)d_in[5];
    const float* bv   = (const float*)d_in[6];
    const float* Wo   = (const float*)d_in[7];
    const float* bo   = (const float*)d_in[8];
    const float* wmix = (const float*)d_in[9];
    float* out = (float*)d_out;

    u16 *q, *k, *v, *c, *x, *wbuf;
    cudaGetSymbolAddress((void**)&q, g_Q);
    cudaGetSymbolAddress((void**)&k, g_K);
    cudaGetSymbolAddress((void**)&v, g_V);
    cudaGetSymbolAddress((void**)&c, g_C);
    cudaGetSymbolAddress((void**)&x, g_X);
    cudaGetSymbolAddress((void**)&wbuf, g_W);

    to_half_pre<<<2048, 256>>>(hs, Wq, Wk, Wv, Wo, x, wbuf);

    cudaFuncSetAttribute(gemm_qkv_h, cudaFuncAttributeMaxDynamicSharedMemorySize, GEMM_SM);
    gemm_qkv_h<<<dim3(D_ / 128, M_TOT / 128, 3), 256, GEMM_SM>>>(
        x, wbuf, bq, bk, bv, q, k, v);

    cudaFuncSetAttribute(attn_h, cudaFuncAttributeMaxDynamicSharedMemorySize, ATT_SM);
    attn_h<<<dim3(S_ / 128, H_, B_), 256, ATT_SM>>>(q, k, v, wmix, c);

    cudaFuncSetAttribute(gemm_out_h, cudaFuncAttributeMaxDynamicSharedMemorySize, GEMM_SM);
    gemm_out_h<<<dim3(D_ / 128, M_TOT / 128), 256, GEMM_SM>>>(
        c, wbuf + 3 * (size_t)DD, bo, out);
}

// round 15
// speedup vs baseline: 1.0274x; 1.0274x over previous
#include <cuda_runtime.h>
#include <cuda_fp16.h>
#include <math.h>
#include <stdint.h>

#define B_ 4
#define S_ 2048
#define D_ 768
#define H_ 12
#define DH_ 64
#define M_TOT (B_ * S_)          // 8192
#define NELEM (M_TOT * D_)       // 6291456
#define DD (D_ * D_)             // 589824

typedef unsigned short u16;
typedef unsigned int u32;

__device__ u16 g_Q[NELEM];
__device__ u16 g_K[NELEM];
__device__ u16 g_V[NELEM];
__device__ u16 g_C[NELEM];
__device__ u16 g_X[NELEM];
__device__ u16 g_W[4 * DD];

// Q prescale: 1/8 (score scale) * log2(e) (exp -> ex2 domain)
#define QSCALE 0.18033688011112042f
// ln2^2: converts (s*log2e)^2 back to s^2 in the relu^2 branch
#define LN2SQ 0.4804530139182014f

// ---------------------------------------------------------------------------
__device__ __forceinline__ u32 h2pack(float lo, float hi) {
    u32 r;
    asm("cvt.rn.f16x2.f32 %0, %1, %2;" : "=r"(r) : "f"(hi), "f"(lo));
    return r;
}

__device__ __forceinline__ u32 ex2h2(u32 x) {
    u32 r;
    asm("ex2.approx.f16x2 %0, %1;" : "=r"(r) : "r"(x));
    return r;
}

__device__ __forceinline__ u32 relusq_h2(u32 x) {
    u32 m, r;
    asm("max.f16x2 %0, %1, %2;" : "=r"(m) : "r"(x), "r"(0u));
    asm("mul.f16x2 %0, %1, %1;" : "=r"(r) : "r"(m));
    return r;
}

__device__ __forceinline__ void mma16(float* c, u32 a0, u32 a1, u32 a2, u32 a3,
                                      u32 b0, u32 b1) {
    asm volatile(
        "mma.sync.aligned.m16n8k16.row.col.f32.f16.f16.f32 "
        "{%0,%1,%2,%3},{%4,%5,%6,%7},{%8,%9},{%0,%1,%2,%3};\n"
        : "+f"(c[0]), "+f"(c[1]), "+f"(c[2]), "+f"(c[3])
        : "r"(a0), "r"(a1), "r"(a2), "r"(a3), "r"(b0), "r"(b1));
}

__device__ __forceinline__ void ldsm4(u32& r0, u32& r1, u32& r2, u32& r3, u32 addr) {
    asm volatile("ldmatrix.sync.aligned.m8n8.x4.shared.b16 {%0,%1,%2,%3}, [%4];"
                 : "=r"(r0), "=r"(r1), "=r"(r2), "=r"(r3) : "r"(addr));
}

__device__ __forceinline__ void ldsm4t(u32& r0, u32& r1, u32& r2, u32& r3, u32 addr) {
    asm volatile("ldmatrix.sync.aligned.m8n8.x4.trans.shared.b16 {%0,%1,%2,%3}, [%4];"
                 : "=r"(r0), "=r"(r1), "=r"(r2), "=r"(r3) : "r"(addr));
}

__device__ __forceinline__ void cp16(unsigned dst, const void* src) {
    asm volatile("cp.async.cg.shared.global [%0], [%1], 16;" :: "r"(dst), "l"(src));
}
#define CP_COMMIT() asm volatile("cp.async.commit_group;")
#define CP_WAIT(N) asm volatile("cp.async.wait_group %0;" :: "n"(N))

__device__ __forceinline__ unsigned smem_u32(const void* p) {
    unsigned a;
    asm("{ .reg .u64 t; cvta.to.shared.u64 t, %1; cvt.u32.u64 %0, t; }" : "=r"(a) : "l"(p));
    return a;
}

// ---------------------------------------------------------------------------
// Prepass: RN-round hidden_states and 4 weights to fp16.
// ---------------------------------------------------------------------------
__global__ void to_half_pre(const float* __restrict__ hs,
                            const float* __restrict__ Wq, const float* __restrict__ Wk,
                            const float* __restrict__ Wv, const float* __restrict__ Wo,
                            u16* __restrict__ X, u16* __restrict__ W)
{
    const int i = blockIdx.x * blockDim.x + threadIdx.x;
    const int stride = gridDim.x * blockDim.x;
    for (int j = i; j < NELEM / 4; j += stride) {
        float4 v = ((const float4*)hs)[j];
        uint2 o = {h2pack(v.x, v.y), h2pack(v.z, v.w)};
        ((uint2*)X)[j] = o;
    }
    const float* src[4] = {Wq, Wk, Wv, Wo};
#pragma unroll
    for (int w = 0; w < 4; w++) {
        const float4* s = (const float4*)src[w];
        uint2* d = (uint2*)(W + (size_t)w * DD);
        for (int j = i; j < DD / 4; j += stride) {
            float4 v = s[j];
            uint2 o = {h2pack(v.x, v.y), h2pack(v.z, v.w)};
            d[j] = o;
        }
    }
}

// ---------------------------------------------------------------------------
// fp16 GEMM v2: 128x128 block tiles, BK=64, 128 threads, 2x2 warp grid with
// 64x64 warp tiles (acc=128 regs) -> MMA:LDSM ratio doubles vs 64x32.
// 3-stage cp.async ring, one barrier per slab (wait -> sync -> prefetch).
// ---------------------------------------------------------------------------
#define GPH 72
#define GSTGH (128 * GPH)
#define GSTGB (GSTGH * 2 * 2)        // bytes per stage (A+B) = 36864
#define GEMM_SM (3 * GSTGB)          // 110592 bytes
#define GTHREADS 128

__device__ __forceinline__ void gemm_h_body(
    const u16* __restrict__ X, const u16* __restrict__ W,
    const float* __restrict__ bi, void* __restrict__ Yp,
    int half_out, float oscale, u16* gsm)
{
    const unsigned sb = smem_u32(gsm);
    const int tid = threadIdx.x;
    const int lane = tid & 31, wid = tid >> 5;
    const int g = lane >> 2, tig = lane & 3;
    const int wy = wid >> 1, wx = wid & 1;     // 2 x 2 warp grid
    const int m0 = blockIdx.y * 128, n0 = blockIdx.x * 128;

#define GH_LOAD(s_) do {                                                        \
        int st_ = (s_) % 3;                                                     \
        unsigned ab_ = sb + st_ * GSTGB;                                        \
        unsigned bb_ = ab_ + GSTGH * 2;                                         \
        _Pragma("unroll")                                                       \
        for (int u_ = 0; u_ < 8; u_++) {                                        \
            int ch_ = tid + u_ * GTHREADS;                                      \
            int r_ = ch_ >> 3, c_ = ch_ & 7;                                    \
            cp16(ab_ + r_ * 144 + c_ * 16,                                      \
                 X + (size_t)(m0 + r_) * D_ + (s_) * 64 + c_ * 8);              \
            cp16(bb_ + r_ * 144 + c_ * 16,                                      \
                 W + (size_t)(n0 + r_) * D_ + (s_) * 64 + c_ * 8);              \
        }                                                                       \
        CP_COMMIT();                                                            \
    } while (0)

    GH_LOAD(0);
    GH_LOAD(1);

    float acc[4][8][4] = {};
    const int NSLAB = D_ / 64;   // 12

    const unsigned a_lrow = (lane & 15) * 144 + (lane >> 4) * 16;
    const unsigned b_lrow = (lane & 7) * 144 + (lane >> 3) * 16;

    for (int s = 0; s < NSLAB; s++) {
        if (s < NSLAB - 2) { CP_WAIT(1); } else { CP_WAIT(0); }
        __syncthreads();
        if (s + 2 < NSLAB) GH_LOAD(s + 2);

        const unsigned ab = sb + (s % 3) * GSTGB;
        const unsigned bb = ab + GSTGH * 2;
        const unsigned abase = ab + (wy * 64) * 144 + a_lrow;
        const unsigned bbase = bb + (wx * 64) * 144 + b_lrow;

#pragma unroll
        for (int ksp = 0; ksp < 2; ksp++) {
            u32 b[8][4];
#pragma unroll
            for (int nt = 0; nt < 8; nt++)
                ldsm4(b[nt][0], b[nt][1], b[nt][2], b[nt][3],
                      bbase + nt * 8 * 144 + ksp * 64);
#pragma unroll
            for (int kh = 0; kh < 2; kh++) {
                const int ks = 2 * ksp + kh;
                u32 a[4][4];
#pragma unroll
                for (int mt = 0; mt < 4; mt++)
                    ldsm4(a[mt][0], a[mt][1], a[mt][2], a[mt][3],
                          abase + mt * 16 * 144 + ks * 32);
#pragma unroll
                for (int mt = 0; mt < 4; mt++)
#pragma unroll
                    for (int nt = 0; nt < 8; nt++)
                        mma16(acc[mt][nt], a[mt][0], a[mt][1], a[mt][2], a[mt][3],
                              b[nt][2 * kh], b[nt][2 * kh + 1]);
            }
        }
    }

#pragma unroll
    for (int nt = 0; nt < 8; nt++) {
        int c = n0 + wx * 64 + nt * 8 + 2 * tig;
        float b0v = bi[c], b1v = bi[c + 1];
#pragma unroll
        for (int mt = 0; mt < 4; mt++) {
            int r = m0 + wy * 64 + mt * 16 + g;
            float o0 = acc[mt][nt][0] + b0v;
            float o1 = acc[mt][nt][1] + b1v;
            float o2 = acc[mt][nt][2] + b0v;
            float o3 = acc[mt][nt][3] + b1v;
            if (half_out) {
                u16* Yh = (u16*)Yp;
                *(u32*)&Yh[(size_t)r * D_ + c] = h2pack(o0 * oscale, o1 * oscale);
                *(u32*)&Yh[(size_t)(r + 8) * D_ + c] = h2pack(o2 * oscale, o3 * oscale);
            } else {
                float* Yf = (float*)Yp;
                float2 q0 = {o0, o1}, q1 = {o2, o3};
                *(float2*)&Yf[(size_t)r * D_ + c] = q0;
                *(float2*)&Yf[(size_t)(r + 8) * D_ + c] = q1;
            }
        }
    }
#undef GH_LOAD
}

__global__ __launch_bounds__(GTHREADS, 2) void gemm_qkv_h(
    const u16* __restrict__ X,
    const u16* __restrict__ Wh, const float* __restrict__ bq,
    const float* __restrict__ bk, const float* __restrict__ bv,
    u16* __restrict__ Yq, u16* __restrict__ Yk, u16* __restrict__ Yv)
{
    extern __shared__ u16 gsm[];
    const u16* W; const float* bi; u16* Y; float sc;
    if (blockIdx.z == 0)      { W = Wh;          bi = bq; Y = Yq; sc = QSCALE; }
    else if (blockIdx.z == 1) { W = Wh + DD;     bi = bk; Y = Yk; sc = 1.0f; }
    else                      { W = Wh + 2 * DD; bi = bv; Y = Yv; sc = 1.0f; }
    gemm_h_body(X, W, bi, Y, 1, sc, gsm);
}

__global__ __launch_bounds__(GTHREADS, 2) void gemm_out_h(
    const u16* __restrict__ X, const u16* __restrict__ Wh,
    const float* __restrict__ bo, float* __restrict__ Y)
{
    extern __shared__ u16 gsm[];
    gemm_h_body(X, Wh, bo, Y, 0, 1.0f, gsm);
}

// ---------------------------------------------------------------------------
// Attention fp16 v6 (R13 exact): 128-row kv tiles, ex2/relusq on f16x2 pipe,
// lsum via ones-column MMA, 3-stage ring, one barrier per tile.
// ---------------------------------------------------------------------------
#define KPH 72
#define KTILE 128
#define KBUFB (KTILE * 144)          // 18432 B per operand stage
#define OFF_VB (3 * KBUFB)
#define ATT_SM (6 * KBUFB)           // 110592 B
#define NKT (S_ / KTILE)             // 16

__global__ __launch_bounds__(256, 2) void attn_h(
    const u16* __restrict__ Q, const u16* __restrict__ K,
    const u16* __restrict__ V, const float* __restrict__ wmix,
    u16* __restrict__ C)
{
    extern __shared__ u16 sm[];
    const unsigned sbase = smem_u32(sm);

    const int tid = threadIdx.x;
    const int lane = tid & 31, w = tid >> 5;
    const int g = lane >> 2, tig = lane & 3;
    const int s0 = blockIdx.x * 128;
    const int h = blockIdx.y;
    const int b = blockIdx.z;
    const size_t base = (size_t)b * S_ * D_ + (size_t)h * DH_;

    const u16* kgb = K + base;
    const u16* vgb = V + base;

    const int lrow = tid >> 3;
    const int lseg = tid & 7;

#define ATT_LOAD(kt_) do {                                                      \
        int st_ = (kt_) % 3;                                                    \
        unsigned sk_ = sbase + st_ * KBUFB;                                     \
        unsigned sv_ = sbase + OFF_VB + st_ * KBUFB;                            \
        const u16* kg_ = kgb + (size_t)(kt_) * KTILE * D_;                      \
        const u16* vg_ = vgb + (size_t)(kt_) * KTILE * D_;                      \
        _Pragma("unroll")                                                       \
        for (int u_ = 0; u_ < 4; u_++) {                                        \
            int row_ = lrow + u_ * 32;                                          \
            cp16(sk_ + row_ * 144 + lseg * 16, kg_ + (size_t)row_ * D_ + lseg * 8); \
            cp16(sv_ + row_ * 144 + lseg * 16, vg_ + (size_t)row_ * D_ + lseg * 8); \
        }                                                                       \
        CP_COMMIT();                                                            \
    } while (0)

    ATT_LOAD(0);
    ATT_LOAD(1);

    // Persistent Q fragments (Q pre-scaled by 0.125*log2e)
    u32 qA[4][4];
    {
        const u16* qp = Q + base + (size_t)(s0 + w * 16 + g) * D_;
        const u16* qp8 = qp + 8 * D_;
#pragma unroll
        for (int ks = 0; ks < 4; ks++) {
            qA[ks][0] = *(const u32*)(qp + ks * 16 + 2 * tig);
            qA[ks][1] = *(const u32*)(qp8 + ks * 16 + 2 * tig);
            qA[ks][2] = *(const u32*)(qp + ks * 16 + 8 + 2 * tig);
            qA[ks][3] = *(const u32*)(qp8 + ks * 16 + 8 + 2 * tig);
        }
    }

    float e0 = __expf(wmix[0]), e1 = __expf(wmix[1]);
    float inv = 1.0f / (e0 + e1);
    const float mix0 = e0 * inv;
    const float mix1l = e1 * inv * LN2SQ;

    float os[8][4] = {};
    float orl[8][4] = {};
    float ls[4] = {};
    const u32 oneb = (g == 0) ? 0x3C003C00u : 0u;

    const unsigned k_lrow = (lane & 7) * 144 + (lane >> 3) * 16;
    const unsigned v_lrow = (lane & 15) * 144 + (lane >> 4) * 16;

    for (int kt = 0; kt < NKT; kt++) {
        if (kt < NKT - 2) { CP_WAIT(1); } else { CP_WAIT(0); }
        __syncthreads();
        if (kt + 2 < NKT) ATT_LOAD(kt + 2);

        const unsigned skb = sbase + (kt % 3) * KBUFB;
        const unsigned svb = sbase + OFF_VB + (kt % 3) * KBUFB;

#pragma unroll
        for (int kvg = 0; kvg < 8; kvg++) {
            float sce[4] = {0.f, 0.f, 0.f, 0.f};
            float sco[4] = {0.f, 0.f, 0.f, 0.f};
            const unsigned kbb = skb + (kvg * 16) * 144 + k_lrow;
#pragma unroll
            for (int ksp = 0; ksp < 2; ksp++) {
                u32 be0, be1, be2, be3, bo0, bo1, bo2, bo3;
                ldsm4(be0, be1, be2, be3, kbb + ksp * 64);
                ldsm4(bo0, bo1, bo2, bo3, kbb + 8 * 144 + ksp * 64);
                const int ks = 2 * ksp;
                mma16(sce, qA[ks][0], qA[ks][1], qA[ks][2], qA[ks][3], be0, be1);
                mma16(sce, qA[ks + 1][0], qA[ks + 1][1], qA[ks + 1][2], qA[ks + 1][3], be2, be3);
                mma16(sco, qA[ks][0], qA[ks][1], qA[ks][2], qA[ks][3], bo0, bo1);
                mma16(sco, qA[ks + 1][0], qA[ks + 1][1], qA[ks + 1][2], qA[ks + 1][3], bo2, bo3);
            }

            // Hoist first V fragment load: overlaps with exp/pack ALU below.
            const unsigned vbb = svb + (kvg * 16) * 144 + v_lrow;
            u32 va0, va1, va2, va3;
            ldsm4t(va0, va1, va2, va3, vbb);

            // Pack once; both branches run on the f16x2 pipe.
            u32 spe0 = h2pack(sce[0], sce[1]);
            u32 spe1 = h2pack(sce[2], sce[3]);
            u32 spo0 = h2pack(sco[0], sco[1]);
            u32 spo1 = h2pack(sco[2], sco[3]);

            u32 ape0 = ex2h2(spe0);
            u32 ape1 = ex2h2(spe1);
            u32 ape2 = ex2h2(spo0);
            u32 ape3 = ex2h2(spo1);

            u32 apq0 = relusq_h2(spe0);
            u32 apq1 = relusq_h2(spe1);
            u32 apq2 = relusq_h2(spo0);
            u32 apq3 = relusq_h2(spo1);

            mma16(ls, ape0, ape1, ape2, ape3, oneb, oneb);

            u32 vb0, vb1, vb2, vb3;
            ldsm4t(vb0, vb1, vb2, vb3, vbb + 32);

            mma16(os[0], ape0, ape1, ape2, ape3, va0, va1);
            mma16(orl[0], apq0, apq1, apq2, apq3, va0, va1);
            mma16(os[1], ape0, ape1, ape2, ape3, va2, va3);
            mma16(orl[1], apq0, apq1, apq2, apq3, va2, va3);

            ldsm4t(va0, va1, va2, va3, vbb + 64);

            mma16(os[2], ape0, ape1, ape2, ape3, vb0, vb1);
            mma16(orl[2], apq0, apq1, apq2, apq3, vb0, vb1);
            mma16(os[3], ape0, ape1, ape2, ape3, vb2, vb3);
            mma16(orl[3], apq0, apq1, apq2, apq3, vb2, vb3);

            ldsm4t(vb0, vb1, vb2, vb3, vbb + 96);

            mma16(os[4], ape0, ape1, ape2, ape3, va0, va1);
            mma16(orl[4], apq0, apq1, apq2, apq3, va0, va1);
            mma16(os[5], ape0, ape1, ape2, ape3, va2, va3);
            mma16(orl[5], apq0, apq1, apq2, apq3, va2, va3);

            mma16(os[6], ape0, ape1, ape2, ape3, vb0, vb1);
            mma16(orl[6], apq0, apq1, apq2, apq3, vb0, vb1);
            mma16(os[7], ape0, ape1, ape2, ape3, vb2, vb3);
            mma16(orl[7], apq0, apq1, apq2, apq3, vb2, vb3);
        }
    }

    float l0 = __shfl_sync(0xffffffffu, ls[0], lane & 28);
    float l1 = __shfl_sync(0xffffffffu, ls[2], lane & 28);
    float f0 = mix0 / l0;
    float f1 = mix0 / l1;

    u16* crow = C + base + (size_t)(s0 + w * 16 + g) * D_;
    u16* crow8 = crow + 8 * D_;
#pragma unroll
    for (int dt = 0; dt < 8; dt++) {
        *(u32*)&crow[dt * 8 + 2 * tig] =
            h2pack(os[dt][0] * f0 + orl[dt][0] * mix1l,
                   os[dt][1] * f0 + orl[dt][1] * mix1l);
        *(u32*)&crow8[dt * 8 + 2 * tig] =
            h2pack(os[dt][2] * f1 + orl[dt][2] * mix1l,
                   os[dt][3] * f1 + orl[dt][3] * mix1l);
    }
#undef ATT_LOAD
}

// ---------------------------------------------------------------------------
extern "C" void kernel_launch(void* const* d_in, const int* in_sizes, int n_in,
                              void* d_out, int out_size)
{
    const float* hs   = (const float*)d_in[0];
    const float* Wq   = (const float*)d_in[1];
    const float* bq   = (const float*)d_in[2];
    const float* Wk   = (const float*)d_in[3];
    const float* bk   = (const float*)d_in[4];
    const float* Wv   = (const float*)d_in[5];
    const float* bv   = (const float*)d_in[6];
    const float* Wo   = (const float*)d_in[7];
    const float* bo   = (const float*)d_in[8];
    const float* wmix = (const float*)d_in[9];
    float* out = (float*)d_out;

    u16 *q, *k, *v, *c, *x, *wbuf;
    cudaGetSymbolAddress((void**)&q, g_Q);
    cudaGetSymbolAddress((void**)&k, g_K);
    cudaGetSymbolAddress((void**)&v, g_V);
    cudaGetSymbolAddress((void**)&c, g_C);
    cudaGetSymbolAddress((void**)&x, g_X);
    cudaGetSymbolAddress((void**)&wbuf, g_W);

    to_half_pre<<<2048, 256>>>(hs, Wq, Wk, Wv, Wo, x, wbuf);

    cudaFuncSetAttribute(gemm_qkv_h, cudaFuncAttributeMaxDynamicSharedMemorySize, GEMM_SM);
    gemm_qkv_h<<<dim3(D_ / 128, M_TOT / 128, 3), GTHREADS, GEMM_SM>>>(
        x, wbuf, bq, bk, bv, q, k, v);

    cudaFuncSetAttribute(attn_h, cudaFuncAttributeMaxDynamicSharedMemorySize, ATT_SM);
    attn_h<<<dim3(S_ / 128, H_, B_), 256, ATT_SM>>>(q, k, v, wmix, c);

    cudaFuncSetAttribute(gemm_out_h, cudaFuncAttributeMaxDynamicSharedMemorySize, GEMM_SM);
    gemm_out_h<<<dim3(D_ / 128, M_TOT / 128), GTHREADS, GEMM_SM>>>(
        c, wbuf + 3 * (size_t)DD, bo, out);
}

// round 16
// speedup vs baseline: 1.0430x; 1.0151x over previous
#include <cuda_runtime.h>
#include <cuda_fp16.h>
#include <math.h>
#include <stdint.h>

#define B_ 4
#define S_ 2048
#define D_ 768
#define H_ 12
#define DH_ 64
#define M_TOT (B_ * S_)          // 8192
#define NELEM (M_TOT * D_)       // 6291456
#define DD (D_ * D_)             // 589824

typedef unsigned short u16;
typedef unsigned int u32;

__device__ u16 g_Q[NELEM];
__device__ u16 g_K[NELEM];
__device__ u16 g_V[NELEM];
__device__ u16 g_C[NELEM];
__device__ u16 g_X[NELEM];
__device__ u16 g_W[4 * DD];

// Q prescale: 1/8 (score scale) * log2(e) (exp -> ex2 domain)
#define QSCALE 0.18033688011112042f
// ln2^2: converts (s*log2e)^2 back to s^2 in the relu^2 branch
#define LN2SQ 0.4804530139182014f

// ---------------------------------------------------------------------------
__device__ __forceinline__ u32 h2pack(float lo, float hi) {
    u32 r;
    asm("cvt.rn.f16x2.f32 %0, %1, %2;" : "=r"(r) : "f"(hi), "f"(lo));
    return r;
}

__device__ __forceinline__ u32 ex2h2(u32 x) {
    u32 r;
    asm("ex2.approx.f16x2 %0, %1;" : "=r"(r) : "r"(x));
    return r;
}

__device__ __forceinline__ u32 relusq_h2(u32 x) {
    u32 m, r;
    asm("max.f16x2 %0, %1, %2;" : "=r"(m) : "r"(x), "r"(0u));
    asm("mul.f16x2 %0, %1, %1;" : "=r"(r) : "r"(m));
    return r;
}

__device__ __forceinline__ void mma16(float* c, u32 a0, u32 a1, u32 a2, u32 a3,
                                      u32 b0, u32 b1) {
    asm volatile(
        "mma.sync.aligned.m16n8k16.row.col.f32.f16.f16.f32 "
        "{%0,%1,%2,%3},{%4,%5,%6,%7},{%8,%9},{%0,%1,%2,%3};\n"
        : "+f"(c[0]), "+f"(c[1]), "+f"(c[2]), "+f"(c[3])
        : "r"(a0), "r"(a1), "r"(a2), "r"(a3), "r"(b0), "r"(b1));
}

__device__ __forceinline__ void ldsm4(u32& r0, u32& r1, u32& r2, u32& r3, u32 addr) {
    asm volatile("ldmatrix.sync.aligned.m8n8.x4.shared.b16 {%0,%1,%2,%3}, [%4];"
                 : "=r"(r0), "=r"(r1), "=r"(r2), "=r"(r3) : "r"(addr));
}

__device__ __forceinline__ void ldsm4t(u32& r0, u32& r1, u32& r2, u32& r3, u32 addr) {
    asm volatile("ldmatrix.sync.aligned.m8n8.x4.trans.shared.b16 {%0,%1,%2,%3}, [%4];"
                 : "=r"(r0), "=r"(r1), "=r"(r2), "=r"(r3) : "r"(addr));
}

__device__ __forceinline__ void cp16(unsigned dst, const void* src) {
    asm volatile("cp.async.cg.shared.global [%0], [%1], 16;" :: "r"(dst), "l"(src));
}
#define CP_COMMIT() asm volatile("cp.async.commit_group;")
#define CP_WAIT(N) asm volatile("cp.async.wait_group %0;" :: "n"(N))

__device__ __forceinline__ unsigned smem_u32(const void* p) {
    unsigned a;
    asm("{ .reg .u64 t; cvta.to.shared.u64 t, %1; cvt.u32.u64 %0, t; }" : "=r"(a) : "l"(p));
    return a;
}

// ---------------------------------------------------------------------------
// Prepass: RN-round hidden_states and 4 weights to fp16.
// ---------------------------------------------------------------------------
__global__ void to_half_pre(const float* __restrict__ hs,
                            const float* __restrict__ Wq, const float* __restrict__ Wk,
                            const float* __restrict__ Wv, const float* __restrict__ Wo,
                            u16* __restrict__ X, u16* __restrict__ W)
{
    const int i = blockIdx.x * blockDim.x + threadIdx.x;
    const int stride = gridDim.x * blockDim.x;
    for (int j = i; j < NELEM / 4; j += stride) {
        float4 v = ((const float4*)hs)[j];
        uint2 o = {h2pack(v.x, v.y), h2pack(v.z, v.w)};
        ((uint2*)X)[j] = o;
    }
    const float* src[4] = {Wq, Wk, Wv, Wo};
#pragma unroll
    for (int w = 0; w < 4; w++) {
        const float4* s = (const float4*)src[w];
        uint2* d = (uint2*)(W + (size_t)w * DD);
        for (int j = i; j < DD / 4; j += stride) {
            float4 v = s[j];
            uint2 o = {h2pack(v.x, v.y), h2pack(v.z, v.w)};
            d[j] = o;
        }
    }
}

// ---------------------------------------------------------------------------
// qkv GEMM (R15 best-known): 128x128 block tiles, BK=64, 128 threads, 2x2
// warp grid with 64x64 warp tiles, padded pitch 144, 3-stage cp.async ring.
// ---------------------------------------------------------------------------
#define GPH 72
#define GSTGH (128 * GPH)
#define GSTGB (GSTGH * 2 * 2)        // bytes per stage (A+B) = 36864
#define GEMM_SM (3 * GSTGB)          // 110592 bytes
#define GTHREADS 128

__global__ __launch_bounds__(GTHREADS, 2) void gemm_qkv_h(
    const u16* __restrict__ X,
    const u16* __restrict__ Wh, const float* __restrict__ bq,
    const float* __restrict__ bk, const float* __restrict__ bv,
    u16* __restrict__ Yq, u16* __restrict__ Yk, u16* __restrict__ Yv)
{
    extern __shared__ u16 gsm[];
    const u16* W; const float* bi; u16* Y; float sc;
    if (blockIdx.z == 0)      { W = Wh;          bi = bq; Y = Yq; sc = QSCALE; }
    else if (blockIdx.z == 1) { W = Wh + DD;     bi = bk; Y = Yk; sc = 1.0f; }
    else                      { W = Wh + 2 * DD; bi = bv; Y = Yv; sc = 1.0f; }

    const unsigned sb = smem_u32(gsm);
    const int tid = threadIdx.x;
    const int lane = tid & 31, wid = tid >> 5;
    const int g = lane >> 2, tig = lane & 3;
    const int wy = wid >> 1, wx = wid & 1;     // 2 x 2 warp grid
    const int m0 = blockIdx.y * 128, n0 = blockIdx.x * 128;

#define GH_LOAD(s_) do {                                                        \
        int st_ = (s_) % 3;                                                     \
        unsigned ab_ = sb + st_ * GSTGB;                                        \
        unsigned bb_ = ab_ + GSTGH * 2;                                         \
        _Pragma("unroll")                                                       \
        for (int u_ = 0; u_ < 8; u_++) {                                        \
            int ch_ = tid + u_ * GTHREADS;                                      \
            int r_ = ch_ >> 3, c_ = ch_ & 7;                                    \
            cp16(ab_ + r_ * 144 + c_ * 16,                                      \
                 X + (size_t)(m0 + r_) * D_ + (s_) * 64 + c_ * 8);              \
            cp16(bb_ + r_ * 144 + c_ * 16,                                      \
                 W + (size_t)(n0 + r_) * D_ + (s_) * 64 + c_ * 8);              \
        }                                                                       \
        CP_COMMIT();                                                            \
    } while (0)

    GH_LOAD(0);
    GH_LOAD(1);

    float acc[4][8][4] = {};
    const int NSLAB = D_ / 64;   // 12

    const unsigned a_lrow = (lane & 15) * 144 + (lane >> 4) * 16;
    const unsigned b_lrow = (lane & 7) * 144 + (lane >> 3) * 16;

    for (int s = 0; s < NSLAB; s++) {
        if (s < NSLAB - 2) { CP_WAIT(1); } else { CP_WAIT(0); }
        __syncthreads();
        if (s + 2 < NSLAB) GH_LOAD(s + 2);

        const unsigned ab = sb + (s % 3) * GSTGB;
        const unsigned bb = ab + GSTGH * 2;
        const unsigned abase = ab + (wy * 64) * 144 + a_lrow;
        const unsigned bbase = bb + (wx * 64) * 144 + b_lrow;

#pragma unroll
        for (int ksp = 0; ksp < 2; ksp++) {
            u32 b[8][4];
#pragma unroll
            for (int nt = 0; nt < 8; nt++)
                ldsm4(b[nt][0], b[nt][1], b[nt][2], b[nt][3],
                      bbase + nt * 8 * 144 + ksp * 64);
#pragma unroll
            for (int kh = 0; kh < 2; kh++) {
                const int ks = 2 * ksp + kh;
                u32 a[4][4];
#pragma unroll
                for (int mt = 0; mt < 4; mt++)
                    ldsm4(a[mt][0], a[mt][1], a[mt][2], a[mt][3],
                          abase + mt * 16 * 144 + ks * 32);
#pragma unroll
                for (int mt = 0; mt < 4; mt++)
#pragma unroll
                    for (int nt = 0; nt < 8; nt++)
                        mma16(acc[mt][nt], a[mt][0], a[mt][1], a[mt][2], a[mt][3],
                              b[nt][2 * kh], b[nt][2 * kh + 1]);
            }
        }
    }

#pragma unroll
    for (int nt = 0; nt < 8; nt++) {
        int c = n0 + wx * 64 + nt * 8 + 2 * tig;
        float b0v = bi[c], b1v = bi[c + 1];
#pragma unroll
        for (int mt = 0; mt < 4; mt++) {
            int r = m0 + wy * 64 + mt * 16 + g;
            float o0 = (acc[mt][nt][0] + b0v) * sc;
            float o1 = (acc[mt][nt][1] + b1v) * sc;
            float o2 = (acc[mt][nt][2] + b0v) * sc;
            float o3 = (acc[mt][nt][3] + b1v) * sc;
            *(u32*)&Y[(size_t)r * D_ + c] = h2pack(o0, o1);
            *(u32*)&Y[(size_t)(r + 8) * D_ + c] = h2pack(o2, o3);
        }
    }
#undef GH_LOAD
}

// ---------------------------------------------------------------------------
// out-GEMM v2: 64x128 block tiles, BK=64, 128 threads, 2x2 warp grid of
// 32x64 warp tiles, XOR-swizzled smem (no padding) -> 3-stage ring fits
// 3 CTAs/SM (24576 B/stage). Grid 768 CTAs / 444 slots = 86.5% fill
// (vs 65% before). f32 output + bias.
// ---------------------------------------------------------------------------
#define OSTGB 24576                  // (64 + 128) rows * 128 B
#define OB_OFF (64 * 128)            // B region starts after A (8192 B)
#define OGEMM_SM (3 * OSTGB)         // 73728 bytes

__global__ __launch_bounds__(128, 3) void gemm_out_h(
    const u16* __restrict__ X, const u16* __restrict__ Wh,
    const float* __restrict__ bo, float* __restrict__ Y)
{
    extern __shared__ u16 gsm[];
    const unsigned sb = smem_u32(gsm);
    const int tid = threadIdx.x;
    const int lane = tid & 31, wid = tid >> 5;
    const int g = lane >> 2, tig = lane & 3;
    const int wy = wid >> 1, wx = wid & 1;     // 2m x 2n warp grid
    const int m0 = blockIdx.y * 64, n0 = blockIdx.x * 128;

#define OG_LOAD(s_) do {                                                        \
        int st_ = (s_) % 3;                                                     \
        unsigned ab_ = sb + st_ * OSTGB;                                        \
        unsigned bb_ = ab_ + OB_OFF;                                            \
        _Pragma("unroll")                                                       \
        for (int u_ = 0; u_ < 4; u_++) {                                        \
            int ch_ = tid + u_ * 128;                                           \
            int r_ = ch_ >> 3, c_ = ch_ & 7;                                    \
            cp16(ab_ + r_ * 128 + ((c_ ^ (r_ & 7)) * 16),                       \
                 X + (size_t)(m0 + r_) * D_ + (s_) * 64 + c_ * 8);              \
        }                                                                       \
        _Pragma("unroll")                                                       \
        for (int u_ = 0; u_ < 8; u_++) {                                        \
            int ch_ = tid + u_ * 128;                                           \
            int r_ = ch_ >> 3, c_ = ch_ & 7;                                    \
            cp16(bb_ + r_ * 128 + ((c_ ^ (r_ & 7)) * 16),                       \
                 Wh + (size_t)(n0 + r_) * D_ + (s_) * 64 + c_ * 8);             \
        }                                                                       \
        CP_COMMIT();                                                            \
    } while (0)

    OG_LOAD(0);
    OG_LOAD(1);

    float acc[2][8][4] = {};
    const int NSLAB = D_ / 64;   // 12
    const int l7 = lane & 7;

    for (int s = 0; s < NSLAB; s++) {
        if (s < NSLAB - 2) { CP_WAIT(1); } else { CP_WAIT(0); }
        __syncthreads();
        if (s + 2 < NSLAB) OG_LOAD(s + 2);

        const unsigned ab = sb + (s % 3) * OSTGB;
        const unsigned bb = ab + OB_OFF;

#pragma unroll
        for (int ksp = 0; ksp < 2; ksp++) {
            u32 b[8][4];
#pragma unroll
            for (int nt = 0; nt < 8; nt++) {
                int row = wx * 64 + nt * 8 + l7;
                int col = ((lane >> 3) + ksp * 4) ^ l7;
                ldsm4(b[nt][0], b[nt][1], b[nt][2], b[nt][3],
                      bb + row * 128 + col * 16);
            }
#pragma unroll
            for (int kh = 0; kh < 2; kh++) {
                const int ks = 2 * ksp + kh;
                u32 a[2][4];
#pragma unroll
                for (int mt = 0; mt < 2; mt++) {
                    int row = wy * 32 + mt * 16 + (lane & 15);
                    int col = ((lane >> 4) + ks * 2) ^ l7;
                    ldsm4(a[mt][0], a[mt][1], a[mt][2], a[mt][3],
                          ab + row * 128 + col * 16);
                }
#pragma unroll
                for (int mt = 0; mt < 2; mt++)
#pragma unroll
                    for (int nt = 0; nt < 8; nt++)
                        mma16(acc[mt][nt], a[mt][0], a[mt][1], a[mt][2], a[mt][3],
                              b[nt][2 * kh], b[nt][2 * kh + 1]);
            }
        }
    }

#pragma unroll
    for (int nt = 0; nt < 8; nt++) {
        int c = n0 + wx * 64 + nt * 8 + 2 * tig;
        float b0v = bo[c], b1v = bo[c + 1];
#pragma unroll
        for (int mt = 0; mt < 2; mt++) {
            int r = m0 + wy * 32 + mt * 16 + g;
            float2 q0 = {acc[mt][nt][0] + b0v, acc[mt][nt][1] + b1v};
            float2 q1 = {acc[mt][nt][2] + b0v, acc[mt][nt][3] + b1v};
            *(float2*)&Y[(size_t)r * D_ + c] = q0;
            *(float2*)&Y[(size_t)(r + 8) * D_ + c] = q1;
        }
    }
#undef OG_LOAD
}

// ---------------------------------------------------------------------------
// Attention fp16 v6 (R13/R15 best-known): 128-row kv tiles, ex2/relusq on
// f16x2 pipe, lsum via ones-column MMA, 3-stage ring, one barrier per tile.
// ---------------------------------------------------------------------------
#define KPH 72
#define KTILE 128
#define KBUFB (KTILE * 144)          // 18432 B per operand stage
#define OFF_VB (3 * KBUFB)
#define ATT_SM (6 * KBUFB)           // 110592 B
#define NKT (S_ / KTILE)             // 16

__global__ __launch_bounds__(256, 2) void attn_h(
    const u16* __restrict__ Q, const u16* __restrict__ K,
    const u16* __restrict__ V, const float* __restrict__ wmix,
    u16* __restrict__ C)
{
    extern __shared__ u16 sm[];
    const unsigned sbase = smem_u32(sm);

    const int tid = threadIdx.x;
    const int lane = tid & 31, w = tid >> 5;
    const int g = lane >> 2, tig = lane & 3;
    const int s0 = blockIdx.x * 128;
    const int h = blockIdx.y;
    const int b = blockIdx.z;
    const size_t base = (size_t)b * S_ * D_ + (size_t)h * DH_;

    const u16* kgb = K + base;
    const u16* vgb = V + base;

    const int lrow = tid >> 3;
    const int lseg = tid & 7;

#define ATT_LOAD(kt_) do {                                                      \
        int st_ = (kt_) % 3;                                                    \
        unsigned sk_ = sbase + st_ * KBUFB;                                     \
        unsigned sv_ = sbase + OFF_VB + st_ * KBUFB;                            \
        const u16* kg_ = kgb + (size_t)(kt_) * KTILE * D_;                      \
        const u16* vg_ = vgb + (size_t)(kt_) * KTILE * D_;                      \
        _Pragma("unroll")                                                       \
        for (int u_ = 0; u_ < 4; u_++) {                                        \
            int row_ = lrow + u_ * 32;                                          \
            cp16(sk_ + row_ * 144 + lseg * 16, kg_ + (size_t)row_ * D_ + lseg * 8); \
            cp16(sv_ + row_ * 144 + lseg * 16, vg_ + (size_t)row_ * D_ + lseg * 8); \
        }                                                                       \
        CP_COMMIT();                                                            \
    } while (0)

    ATT_LOAD(0);
    ATT_LOAD(1);

    u32 qA[4][4];
    {
        const u16* qp = Q + base + (size_t)(s0 + w * 16 + g) * D_;
        const u16* qp8 = qp + 8 * D_;
#pragma unroll
        for (int ks = 0; ks < 4; ks++) {
            qA[ks][0] = *(const u32*)(qp + ks * 16 + 2 * tig);
            qA[ks][1] = *(const u32*)(qp8 + ks * 16 + 2 * tig);
            qA[ks][2] = *(const u32*)(qp + ks * 16 + 8 + 2 * tig);
            qA[ks][3] = *(const u32*)(qp8 + ks * 16 + 8 + 2 * tig);
        }
    }

    float e0 = __expf(wmix[0]), e1 = __expf(wmix[1]);
    float inv = 1.0f / (e0 + e1);
    const float mix0 = e0 * inv;
    const float mix1l = e1 * inv * LN2SQ;

    float os[8][4] = {};
    float orl[8][4] = {};
    float ls[4] = {};
    const u32 oneb = (g == 0) ? 0x3C003C00u : 0u;

    const unsigned k_lrow = (lane & 7) * 144 + (lane >> 3) * 16;
    const unsigned v_lrow = (lane & 15) * 144 + (lane >> 4) * 16;

    for (int kt = 0; kt < NKT; kt++) {
        if (kt < NKT - 2) { CP_WAIT(1); } else { CP_WAIT(0); }
        __syncthreads();
        if (kt + 2 < NKT) ATT_LOAD(kt + 2);

        const unsigned skb = sbase + (kt % 3) * KBUFB;
        const unsigned svb = sbase + OFF_VB + (kt % 3) * KBUFB;

#pragma unroll
        for (int kvg = 0; kvg < 8; kvg++) {
            float sce[4] = {0.f, 0.f, 0.f, 0.f};
            float sco[4] = {0.f, 0.f, 0.f, 0.f};
            const unsigned kbb = skb + (kvg * 16) * 144 + k_lrow;
#pragma unroll
            for (int ksp = 0; ksp < 2; ksp++) {
                u32 be0, be1, be2, be3, bo0, bo1, bo2, bo3;
                ldsm4(be0, be1, be2, be3, kbb + ksp * 64);
                ldsm4(bo0, bo1, bo2, bo3, kbb + 8 * 144 + ksp * 64);
                const int ks = 2 * ksp;
                mma16(sce, qA[ks][0], qA[ks][1], qA[ks][2], qA[ks][3], be0, be1);
                mma16(sce, qA[ks + 1][0], qA[ks + 1][1], qA[ks + 1][2], qA[ks + 1][3], be2, be3);
                mma16(sco, qA[ks][0], qA[ks][1], qA[ks][2], qA[ks][3], bo0, bo1);
                mma16(sco, qA[ks + 1][0], qA[ks + 1][1], qA[ks + 1][2], qA[ks + 1][3], bo2, bo3);
            }

            const unsigned vbb = svb + (kvg * 16) * 144 + v_lrow;
            u32 va0, va1, va2, va3;
            ldsm4t(va0, va1, va2, va3, vbb);

            u32 spe0 = h2pack(sce[0], sce[1]);
            u32 spe1 = h2pack(sce[2], sce[3]);
            u32 spo0 = h2pack(sco[0], sco[1]);
            u32 spo1 = h2pack(sco[2], sco[3]);

            u32 ape0 = ex2h2(spe0);
            u32 ape1 = ex2h2(spe1);
            u32 ape2 = ex2h2(spo0);
            u32 ape3 = ex2h2(spo1);

            u32 apq0 = relusq_h2(spe0);
            u32 apq1 = relusq_h2(spe1);
            u32 apq2 = relusq_h2(spo0);
            u32 apq3 = relusq_h2(spo1);

            mma16(ls, ape0, ape1, ape2, ape3, oneb, oneb);

            u32 vb0, vb1, vb2, vb3;
            ldsm4t(vb0, vb1, vb2, vb3, vbb + 32);

            mma16(os[0], ape0, ape1, ape2, ape3, va0, va1);
            mma16(orl[0], apq0, apq1, apq2, apq3, va0, va1);
            mma16(os[1], ape0, ape1, ape2, ape3, va2, va3);
            mma16(orl[1], apq0, apq1, apq2, apq3, va2, va3);

            ldsm4t(va0, va1, va2, va3, vbb + 64);

            mma16(os[2], ape0, ape1, ape2, ape3, vb0, vb1);
            mma16(orl[2], apq0, apq1, apq2, apq3, vb0, vb1);
            mma16(os[3], ape0, ape1, ape2, ape3, vb2, vb3);
            mma16(orl[3], apq0, apq1, apq2, apq3, vb2, vb3);

            ldsm4t(vb0, vb1, vb2, vb3, vbb + 96);

            mma16(os[4], ape0, ape1, ape2, ape3, va0, va1);
            mma16(orl[4], apq0, apq1, apq2, apq3, va0, va1);
            mma16(os[5], ape0, ape1, ape2, ape3, va2, va3);
            mma16(orl[5], apq0, apq1, apq2, apq3, va2, va3);

            mma16(os[6], ape0, ape1, ape2, ape3, vb0, vb1);
            mma16(orl[6], apq0, apq1, apq2, apq3, vb0, vb1);
            mma16(os[7], ape0, ape1, ape2, ape3, vb2, vb3);
            mma16(orl[7], apq0, apq1, apq2, apq3, vb2, vb3);
        }
    }

    float l0 = __shfl_sync(0xffffffffu, ls[0], lane & 28);
    float l1 = __shfl_sync(0xffffffffu, ls[2], lane & 28);
    float f0 = mix0 / l0;
    float f1 = mix0 / l1;

    u16* crow = C + base + (size_t)(s0 + w * 16 + g) * D_;
    u16* crow8 = crow + 8 * D_;
#pragma unroll
    for (int dt = 0; dt < 8; dt++) {
        *(u32*)&crow[dt * 8 + 2 * tig] =
            h2pack(os[dt][0] * f0 + orl[dt][0] * mix1l,
                   os[dt][1] * f0 + orl[dt][1] * mix1l);
        *(u32*)&crow8[dt * 8 + 2 * tig] =
            h2pack(os[dt][2] * f1 + orl[dt][2] * mix1l,
                   os[dt][3] * f1 + orl[dt][3] * mix1l);
    }
#undef ATT_LOAD
}

// ---------------------------------------------------------------------------
extern "C" void kernel_launch(void* const* d_in, const int* in_sizes, int n_in,
                              void* d_out, int out_size)
{
    const float* hs   = (const float*)d_in[0];
    const float* Wq   = (const float*)d_in[1];
    const float* bq   = (const float*)d_in[2];
    const float* Wk   = (const float*)d_in[3];
    const float* bk   = (const float*)d_in[4];
    const float* Wv   = (const float*)d_in[5];
    const float* bv   = (const float*)d_in[6];
    const float* Wo   = (const float*)d_in[7];
    const float* bo   = (const float*)d_in[8];
    const float* wmix = (const float*)d_in[9];
    float* out = (float*)d_out;

    u16 *q, *k, *v, *c, *x, *wbuf;
    cudaGetSymbolAddress((void**)&q, g_Q);
    cudaGetSymbolAddress((void**)&k, g_K);
    cudaGetSymbolAddress((void**)&v, g_V);
    cudaGetSymbolAddress((void**)&c, g_C);
    cudaGetSymbolAddress((void**)&x, g_X);
    cudaGetSymbolAddress((void**)&wbuf, g_W);

    to_half_pre<<<2048, 256>>>(hs, Wq, Wk, Wv, Wo, x, wbuf);

    cudaFuncSetAttribute(gemm_qkv_h, cudaFuncAttributeMaxDynamicSharedMemorySize, GEMM_SM);
    gemm_qkv_h<<<dim3(D_ / 128, M_TOT / 128, 3), GTHREADS, GEMM_SM>>>(
        x, wbuf, bq, bk, bv, q, k, v);

    cudaFuncSetAttribute(attn_h, cudaFuncAttributeMaxDynamicSharedMemorySize, ATT_SM);
    attn_h<<<dim3(S_ / 128, H_, B_), 256, ATT_SM>>>(q, k, v, wmix, c);

    cudaFuncSetAttribute(gemm_out_h, cudaFuncAttributeMaxDynamicSharedMemorySize, OGEMM_SM);
    gemm_out_h<<<dim3(D_ / 128, M_TOT / 64), 128, OGEMM_SM>>>(
        c, wbuf + 3 * (size_t)DD, bo, out);
}

// round 17
// speedup vs baseline: 1.0583x; 1.0148x over previous
#include <cuda_runtime.h>
#include <cuda_fp16.h>
#include <math.h>
#include <stdint.h>

#define B_ 4
#define S_ 2048
#define D_ 768
#define H_ 12
#define DH_ 64
#define M_TOT (B_ * S_)          // 8192
#define NELEM (M_TOT * D_)       // 6291456
#define DD (D_ * D_)             // 589824

typedef unsigned short u16;
typedef unsigned int u32;

__device__ u16 g_Q[NELEM];
__device__ u16 g_K[NELEM];
__device__ u16 g_V[NELEM];
__device__ u16 g_C[NELEM];
__device__ u16 g_X[NELEM];
__device__ u16 g_W[4 * DD];

// Q prescale: 1/8 (score scale) * log2(e) (exp -> ex2 domain)
#define QSCALE 0.18033688011112042f
// ln2^2: converts (s*log2e)^2 back to s^2 in the relu^2 branch
#define LN2SQ 0.4804530139182014f

// ---------------------------------------------------------------------------
__device__ __forceinline__ u32 h2pack(float lo, float hi) {
    u32 r;
    asm("cvt.rn.f16x2.f32 %0, %1, %2;" : "=r"(r) : "f"(hi), "f"(lo));
    return r;
}

__device__ __forceinline__ u32 ex2h2(u32 x) {
    u32 r;
    asm("ex2.approx.f16x2 %0, %1;" : "=r"(r) : "r"(x));
    return r;
}

__device__ __forceinline__ u32 relusq_h2(u32 x) {
    u32 m, r;
    asm("max.f16x2 %0, %1, %2;" : "=r"(m) : "r"(x), "r"(0u));
    asm("mul.f16x2 %0, %1, %1;" : "=r"(r) : "r"(m));
    return r;
}

__device__ __forceinline__ void mma16(float* c, u32 a0, u32 a1, u32 a2, u32 a3,
                                      u32 b0, u32 b1) {
    asm volatile(
        "mma.sync.aligned.m16n8k16.row.col.f32.f16.f16.f32 "
        "{%0,%1,%2,%3},{%4,%5,%6,%7},{%8,%9},{%0,%1,%2,%3};\n"
        : "+f"(c[0]), "+f"(c[1]), "+f"(c[2]), "+f"(c[3])
        : "r"(a0), "r"(a1), "r"(a2), "r"(a3), "r"(b0), "r"(b1));
}

__device__ __forceinline__ void ldsm4(u32& r0, u32& r1, u32& r2, u32& r3, u32 addr) {
    asm volatile("ldmatrix.sync.aligned.m8n8.x4.shared.b16 {%0,%1,%2,%3}, [%4];"
                 : "=r"(r0), "=r"(r1), "=r"(r2), "=r"(r3) : "r"(addr));
}

__device__ __forceinline__ void ldsm4t(u32& r0, u32& r1, u32& r2, u32& r3, u32 addr) {
    asm volatile("ldmatrix.sync.aligned.m8n8.x4.trans.shared.b16 {%0,%1,%2,%3}, [%4];"
                 : "=r"(r0), "=r"(r1), "=r"(r2), "=r"(r3) : "r"(addr));
}

__device__ __forceinline__ void cp16(unsigned dst, const void* src) {
    asm volatile("cp.async.cg.shared.global [%0], [%1], 16;" :: "r"(dst), "l"(src));
}
#define CP_COMMIT() asm volatile("cp.async.commit_group;")
#define CP_WAIT(N) asm volatile("cp.async.wait_group %0;" :: "n"(N))

__device__ __forceinline__ unsigned smem_u32(const void* p) {
    unsigned a;
    asm("{ .reg .u64 t; cvta.to.shared.u64 t, %1; cvt.u32.u64 %0, t; }" : "=r"(a) : "l"(p));
    return a;
}

// ---------------------------------------------------------------------------
// Prepass: RN-round hidden_states and 4 weights to fp16.
// ---------------------------------------------------------------------------
__global__ void to_half_pre(const float* __restrict__ hs,
                            const float* __restrict__ Wq, const float* __restrict__ Wk,
                            const float* __restrict__ Wv, const float* __restrict__ Wo,
                            u16* __restrict__ X, u16* __restrict__ W)
{
    const int i = blockIdx.x * blockDim.x + threadIdx.x;
    const int stride = gridDim.x * blockDim.x;
    for (int j = i; j < NELEM / 4; j += stride) {
        float4 v = ((const float4*)hs)[j];
        uint2 o = {h2pack(v.x, v.y), h2pack(v.z, v.w)};
        ((uint2*)X)[j] = o;
    }
    const float* src[4] = {Wq, Wk, Wv, Wo};
#pragma unroll
    for (int w = 0; w < 4; w++) {
        const float4* s = (const float4*)src[w];
        uint2* d = (uint2*)(W + (size_t)w * DD);
        for (int j = i; j < DD / 4; j += stride) {
            float4 v = s[j];
            uint2 o = {h2pack(v.x, v.y), h2pack(v.z, v.w)};
            d[j] = o;
        }
    }
}

// ---------------------------------------------------------------------------
// GEMM v2 core: 64x128 block tiles, BK=64, 128 threads, 2x2 warp grid of
// 32x64 warp tiles, XOR-swizzled smem (no padding), 3-stage cp.async ring,
// 3 CTAs/SM. Used for BOTH qkv (fp16 out, scaled) and out-proj (f32 out).
// ---------------------------------------------------------------------------
#define OSTGB 24576                  // (64 + 128) rows * 128 B
#define OB_OFF (64 * 128)            // B region starts after A (8192 B)
#define OGEMM_SM (3 * OSTGB)         // 73728 bytes

__device__ __forceinline__ void gemm_v2_body(
    const u16* __restrict__ X, const u16* __restrict__ W,
    const float* __restrict__ bi, void* __restrict__ Yp,
    int half_out, float oscale, u16* gsm)
{
    const unsigned sb = smem_u32(gsm);
    const int tid = threadIdx.x;
    const int lane = tid & 31, wid = tid >> 5;
    const int g = lane >> 2, tig = lane & 3;
    const int wy = wid >> 1, wx = wid & 1;     // 2m x 2n warp grid
    const int m0 = blockIdx.y * 64, n0 = blockIdx.x * 128;

#define OG_LOAD(s_) do {                                                        \
        int st_ = (s_) % 3;                                                     \
        unsigned ab_ = sb + st_ * OSTGB;                                        \
        unsigned bb_ = ab_ + OB_OFF;                                            \
        _Pragma("unroll")                                                       \
        for (int u_ = 0; u_ < 4; u_++) {                                        \
            int ch_ = tid + u_ * 128;                                           \
            int r_ = ch_ >> 3, c_ = ch_ & 7;                                    \
            cp16(ab_ + r_ * 128 + ((c_ ^ (r_ & 7)) * 16),                       \
                 X + (size_t)(m0 + r_) * D_ + (s_) * 64 + c_ * 8);              \
        }                                                                       \
        _Pragma("unroll")                                                       \
        for (int u_ = 0; u_ < 8; u_++) {                                        \
            int ch_ = tid + u_ * 128;                                           \
            int r_ = ch_ >> 3, c_ = ch_ & 7;                                    \
            cp16(bb_ + r_ * 128 + ((c_ ^ (r_ & 7)) * 16),                       \
                 W + (size_t)(n0 + r_) * D_ + (s_) * 64 + c_ * 8);              \
        }                                                                       \
        CP_COMMIT();                                                            \
    } while (0)

    OG_LOAD(0);
    OG_LOAD(1);

    float acc[2][8][4] = {};
    const int NSLAB = D_ / 64;   // 12
    const int l7 = lane & 7;

    for (int s = 0; s < NSLAB; s++) {
        if (s < NSLAB - 2) { CP_WAIT(1); } else { CP_WAIT(0); }
        __syncthreads();
        if (s + 2 < NSLAB) OG_LOAD(s + 2);

        const unsigned ab = sb + (s % 3) * OSTGB;
        const unsigned bb = ab + OB_OFF;

#pragma unroll
        for (int ksp = 0; ksp < 2; ksp++) {
            u32 b[8][4];
#pragma unroll
            for (int nt = 0; nt < 8; nt++) {
                int row = wx * 64 + nt * 8 + l7;
                int col = ((lane >> 3) + ksp * 4) ^ l7;
                ldsm4(b[nt][0], b[nt][1], b[nt][2], b[nt][3],
                      bb + row * 128 + col * 16);
            }
#pragma unroll
            for (int kh = 0; kh < 2; kh++) {
                const int ks = 2 * ksp + kh;
                u32 a[2][4];
#pragma unroll
                for (int mt = 0; mt < 2; mt++) {
                    int row = wy * 32 + mt * 16 + (lane & 15);
                    int col = ((lane >> 4) + ks * 2) ^ l7;
                    ldsm4(a[mt][0], a[mt][1], a[mt][2], a[mt][3],
                          ab + row * 128 + col * 16);
                }
#pragma unroll
                for (int mt = 0; mt < 2; mt++)
#pragma unroll
                    for (int nt = 0; nt < 8; nt++)
                        mma16(acc[mt][nt], a[mt][0], a[mt][1], a[mt][2], a[mt][3],
                              b[nt][2 * kh], b[nt][2 * kh + 1]);
            }
        }
    }

#pragma unroll
    for (int nt = 0; nt < 8; nt++) {
        int c = n0 + wx * 64 + nt * 8 + 2 * tig;
        float b0v = bi[c], b1v = bi[c + 1];
#pragma unroll
        for (int mt = 0; mt < 2; mt++) {
            int r = m0 + wy * 32 + mt * 16 + g;
            float o0 = acc[mt][nt][0] + b0v;
            float o1 = acc[mt][nt][1] + b1v;
            float o2 = acc[mt][nt][2] + b0v;
            float o3 = acc[mt][nt][3] + b1v;
            if (half_out) {
                u16* Yh = (u16*)Yp;
                *(u32*)&Yh[(size_t)r * D_ + c] = h2pack(o0 * oscale, o1 * oscale);
                *(u32*)&Yh[(size_t)(r + 8) * D_ + c] = h2pack(o2 * oscale, o3 * oscale);
            } else {
                float* Yf = (float*)Yp;
                float2 q0 = {o0, o1}, q1 = {o2, o3};
                *(float2*)&Yf[(size_t)r * D_ + c] = q0;
                *(float2*)&Yf[(size_t)(r + 8) * D_ + c] = q1;
            }
        }
    }
#undef OG_LOAD
}

__global__ __launch_bounds__(128, 3) void gemm_qkv_h(
    const u16* __restrict__ X,
    const u16* __restrict__ Wh, const float* __restrict__ bq,
    const float* __restrict__ bk, const float* __restrict__ bv,
    u16* __restrict__ Yq, u16* __restrict__ Yk, u16* __restrict__ Yv)
{
    extern __shared__ u16 gsm[];
    const u16* W; const float* bi; u16* Y; float sc;
    if (blockIdx.z == 0)      { W = Wh;          bi = bq; Y = Yq; sc = QSCALE; }
    else if (blockIdx.z == 1) { W = Wh + DD;     bi = bk; Y = Yk; sc = 1.0f; }
    else                      { W = Wh + 2 * DD; bi = bv; Y = Yv; sc = 1.0f; }
    gemm_v2_body(X, W, bi, Y, 1, sc, gsm);
}

__global__ __launch_bounds__(128, 3) void gemm_out_h(
    const u16* __restrict__ X, const u16* __restrict__ Wh,
    const float* __restrict__ bo, float* __restrict__ Y)
{
    extern __shared__ u16 gsm[];
    gemm_v2_body(X, Wh, bo, Y, 0, 1.0f, gsm);
}

// ---------------------------------------------------------------------------
// Attention fp16 v6 (best-known): 128-row kv tiles, ex2/relusq on f16x2 pipe,
// lsum via ones-column MMA, 3-stage ring, one barrier per tile.
// ---------------------------------------------------------------------------
#define KPH 72
#define KTILE 128
#define KBUFB (KTILE * 144)          // 18432 B per operand stage
#define OFF_VB (3 * KBUFB)
#define ATT_SM (6 * KBUFB)           // 110592 B
#define NKT (S_ / KTILE)             // 16

__global__ __launch_bounds__(256, 2) void attn_h(
    const u16* __restrict__ Q, const u16* __restrict__ K,
    const u16* __restrict__ V, const float* __restrict__ wmix,
    u16* __restrict__ C)
{
    extern __shared__ u16 sm[];
    const unsigned sbase = smem_u32(sm);

    const int tid = threadIdx.x;
    const int lane = tid & 31, w = tid >> 5;
    const int g = lane >> 2, tig = lane & 3;
    const int s0 = blockIdx.x * 128;
    const int h = blockIdx.y;
    const int b = blockIdx.z;
    const size_t base = (size_t)b * S_ * D_ + (size_t)h * DH_;

    const u16* kgb = K + base;
    const u16* vgb = V + base;

    const int lrow = tid >> 3;
    const int lseg = tid & 7;

#define ATT_LOAD(kt_) do {                                                      \
        int st_ = (kt_) % 3;                                                    \
        unsigned sk_ = sbase + st_ * KBUFB;                                     \
        unsigned sv_ = sbase + OFF_VB + st_ * KBUFB;                            \
        const u16* kg_ = kgb + (size_t)(kt_) * KTILE * D_;                      \
        const u16* vg_ = vgb + (size_t)(kt_) * KTILE * D_;                      \
        _Pragma("unroll")                                                       \
        for (int u_ = 0; u_ < 4; u_++) {                                        \
            int row_ = lrow + u_ * 32;                                          \
            cp16(sk_ + row_ * 144 + lseg * 16, kg_ + (size_t)row_ * D_ + lseg * 8); \
            cp16(sv_ + row_ * 144 + lseg * 16, vg_ + (size_t)row_ * D_ + lseg * 8); \
        }                                                                       \
        CP_COMMIT();                                                            \
    } while (0)

    ATT_LOAD(0);
    ATT_LOAD(1);

    u32 qA[4][4];
    {
        const u16* qp = Q + base + (size_t)(s0 + w * 16 + g) * D_;
        const u16* qp8 = qp + 8 * D_;
#pragma unroll
        for (int ks = 0; ks < 4; ks++) {
            qA[ks][0] = *(const u32*)(qp + ks * 16 + 2 * tig);
            qA[ks][1] = *(const u32*)(qp8 + ks * 16 + 2 * tig);
            qA[ks][2] = *(const u32*)(qp + ks * 16 + 8 + 2 * tig);
            qA[ks][3] = *(const u32*)(qp8 + ks * 16 + 8 + 2 * tig);
        }
    }

    float e0 = __expf(wmix[0]), e1 = __expf(wmix[1]);
    float inv = 1.0f / (e0 + e1);
    const float mix0 = e0 * inv;
    const float mix1l = e1 * inv * LN2SQ;

    float os[8][4] = {};
    float orl[8][4] = {};
    float ls[4] = {};
    const u32 oneb = (g == 0) ? 0x3C003C00u : 0u;

    const unsigned k_lrow = (lane & 7) * 144 + (lane >> 3) * 16;
    const unsigned v_lrow = (lane & 15) * 144 + (lane >> 4) * 16;

    for (int kt = 0; kt < NKT; kt++) {
        if (kt < NKT - 2) { CP_WAIT(1); } else { CP_WAIT(0); }
        __syncthreads();
        if (kt + 2 < NKT) ATT_LOAD(kt + 2);

        const unsigned skb = sbase + (kt % 3) * KBUFB;
        const unsigned svb = sbase + OFF_VB + (kt % 3) * KBUFB;

#pragma unroll
        for (int kvg = 0; kvg < 8; kvg++) {
            float sce[4] = {0.f, 0.f, 0.f, 0.f};
            float sco[4] = {0.f, 0.f, 0.f, 0.f};
            const unsigned kbb = skb + (kvg * 16) * 144 + k_lrow;
#pragma unroll
            for (int ksp = 0; ksp < 2; ksp++) {
                u32 be0, be1, be2, be3, bo0, bo1, bo2, bo3;
                ldsm4(be0, be1, be2, be3, kbb + ksp * 64);
                ldsm4(bo0, bo1, bo2, bo3, kbb + 8 * 144 + ksp * 64);
                const int ks = 2 * ksp;
                mma16(sce, qA[ks][0], qA[ks][1], qA[ks][2], qA[ks][3], be0, be1);
                mma16(sce, qA[ks + 1][0], qA[ks + 1][1], qA[ks + 1][2], qA[ks + 1][3], be2, be3);
                mma16(sco, qA[ks][0], qA[ks][1], qA[ks][2], qA[ks][3], bo0, bo1);
                mma16(sco, qA[ks + 1][0], qA[ks + 1][1], qA[ks + 1][2], qA[ks + 1][3], bo2, bo3);
            }

            const unsigned vbb = svb + (kvg * 16) * 144 + v_lrow;
            u32 va0, va1, va2, va3;
            ldsm4t(va0, va1, va2, va3, vbb);

            u32 spe0 = h2pack(sce[0], sce[1]);
            u32 spe1 = h2pack(sce[2], sce[3]);
            u32 spo0 = h2pack(sco[0], sco[1]);
            u32 spo1 = h2pack(sco[2], sco[3]);

            u32 ape0 = ex2h2(spe0);
            u32 ape1 = ex2h2(spe1);
            u32 ape2 = ex2h2(spo0);
            u32 ape3 = ex2h2(spo1);

            u32 apq0 = relusq_h2(spe0);
            u32 apq1 = relusq_h2(spe1);
            u32 apq2 = relusq_h2(spo0);
            u32 apq3 = relusq_h2(spo1);

            mma16(ls, ape0, ape1, ape2, ape3, oneb, oneb);

            u32 vb0, vb1, vb2, vb3;
            ldsm4t(vb0, vb1, vb2, vb3, vbb + 32);

            mma16(os[0], ape0, ape1, ape2, ape3, va0, va1);
            mma16(orl[0], apq0, apq1, apq2, apq3, va0, va1);
            mma16(os[1], ape0, ape1, ape2, ape3, va2, va3);
            mma16(orl[1], apq0, apq1, apq2, apq3, va2, va3);

            ldsm4t(va0, va1, va2, va3, vbb + 64);

            mma16(os[2], ape0, ape1, ape2, ape3, vb0, vb1);
            mma16(orl[2], apq0, apq1, apq2, apq3, vb0, vb1);
            mma16(os[3], ape0, ape1, ape2, ape3, vb2, vb3);
            mma16(orl[3], apq0, apq1, apq2, apq3, vb2, vb3);

            ldsm4t(vb0, vb1, vb2, vb3, vbb + 96);

            mma16(os[4], ape0, ape1, ape2, ape3, va0, va1);
            mma16(orl[4], apq0, apq1, apq2, apq3, va0, va1);
            mma16(os[5], ape0, ape1, ape2, ape3, va2, va3);
            mma16(orl[5], apq0, apq1, apq2, apq3, va2, va3);

            mma16(os[6], ape0, ape1, ape2, ape3, vb0, vb1);
            mma16(orl[6], apq0, apq1, apq2, apq3, vb0, vb1);
            mma16(os[7], ape0, ape1, ape2, ape3, vb2, vb3);
            mma16(orl[7], apq0, apq1, apq2, apq3, vb2, vb3);
        }
    }

    float l0 = __shfl_sync(0xffffffffu, ls[0], lane & 28);
    float l1 = __shfl_sync(0xffffffffu, ls[2], lane & 28);
    float f0 = mix0 / l0;
    float f1 = mix0 / l1;

    u16* crow = C + base + (size_t)(s0 + w * 16 + g) * D_;
    u16* crow8 = crow + 8 * D_;
#pragma unroll
    for (int dt = 0; dt < 8; dt++) {
        *(u32*)&crow[dt * 8 + 2 * tig] =
            h2pack(os[dt][0] * f0 + orl[dt][0] * mix1l,
                   os[dt][1] * f0 + orl[dt][1] * mix1l);
        *(u32*)&crow8[dt * 8 + 2 * tig] =
            h2pack(os[dt][2] * f1 + orl[dt][2] * mix1l,
                   os[dt][3] * f1 + orl[dt][3] * mix1l);
    }
#undef ATT_LOAD
}

// ---------------------------------------------------------------------------
extern "C" void kernel_launch(void* const* d_in, const int* in_sizes, int n_in,
                              void* d_out, int out_size)
{
    const float* hs   = (const float*)d_in[0];
    const float* Wq   = (const float*)d_in[1];
    const float* bq   = (const float*)d_in[2];
    const float* Wk   = (const float*)d_in[3];
    const float* bk   = (const float*)d_in[4];
    const float* Wv   = (const float*)d_in[5];
    const float* bv   = (const float*)d_in[6];
    const float* Wo   = (const float*)d_in[7];
    const float* bo   = (const float*)d_in[8];
    const float* wmix = (const float*)d_in[9];
    float* out = (float*)d_out;

    u16 *q, *k, *v, *c, *x, *wbuf;
    cudaGetSymbolAddress((void**)&q, g_Q);
    cudaGetSymbolAddress((void**)&k, g_K);
    cudaGetSymbolAddress((void**)&v, g_V);
    cudaGetSymbolAddress((void**)&c, g_C);
    cudaGetSymbolAddress((void**)&x, g_X);
    cudaGetSymbolAddress((void**)&wbuf, g_W);

    to_half_pre<<<2048, 256>>>(hs, Wq, Wk, Wv, Wo, x, wbuf);

    cudaFuncSetAttribute(gemm_qkv_h, cudaFuncAttributeMaxDynamicSharedMemorySize, OGEMM_SM);
    gemm_qkv_h<<<dim3(D_ / 128, M_TOT / 64, 3), 128, OGEMM_SM>>>(
        x, wbuf, bq, bk, bv, q, k, v);

    cudaFuncSetAttribute(attn_h, cudaFuncAttributeMaxDynamicSharedMemorySize, ATT_SM);
    attn_h<<<dim3(S_ / 128, H_, B_), 256, ATT_SM>>>(q, k, v, wmix, c);

    cudaFuncSetAttribute(gemm_out_h, cudaFuncAttributeMaxDynamicSharedMemorySize, OGEMM_SM);
    gemm_out_h<<<dim3(D_ / 128, M_TOT / 64), 128, OGEMM_SM>>>(
        c, wbuf + 3 * (size_t)DD, bo, out);
}